// round 1
// baseline (speedup 1.0000x reference)
#include <cuda_runtime.h>
#include <cuda_bf16.h>

// Problem: B=2, N=1024, C=128, H1=128, H2=64
//   aL[b,i,h] = sum_c x[b,i,c]*W1[c,h] + b1[h]
//   aR[b,j,h] = sum_c x[b,j,c]*W1[C+c,h]
//   h1 = relu(aL_i + aR_j)          [128]
//   h2 = relu(h1 @ W2 + b2)         [64]
//   y[b,i,j] = h2 @ W3 + b3   for j > i, else 0

#define Bb 2
#define Nn 1024
#define Cc 128
#define H1 128
#define H2 64

// scratch: aL, aR  (2*1024*128 floats each = 1 MB each)
__device__ float g_aL[Bb * Nn * H1];
__device__ float g_aR[Bb * Nn * H1];

// ---------------------------------------------------------------------------
// Kernel 0: zero-fill output (masked entries must be exactly 0; out is poisoned)
// ---------------------------------------------------------------------------
__global__ void zero_fill_kernel(float4* out, int n4) {
    int i = blockIdx.x * blockDim.x + threadIdx.x;
    if (i < n4) out[i] = make_float4(0.f, 0.f, 0.f, 0.f);
}

// ---------------------------------------------------------------------------
// Kernel 1: precompute aL (with b1 folded in) and aR.
// One CTA per token row (b*N+i), 128 threads = one h each.
// ---------------------------------------------------------------------------
__global__ void precompute_kernel(const float* __restrict__ x,
                                  const float* __restrict__ W1,
                                  const float* __restrict__ b1) {
    int row = blockIdx.x;          // 0 .. B*N-1
    int h = threadIdx.x;           // 0 .. 127
    __shared__ float sx[Cc];
    sx[h] = x[row * Cc + h];
    __syncthreads();

    float sL = b1[h];
    float sR = 0.f;
#pragma unroll 8
    for (int c = 0; c < Cc; c++) {
        float xv = sx[c];
        sL = fmaf(xv, W1[c * H1 + h], sL);
        sR = fmaf(xv, W1[(Cc + c) * H1 + h], sR);
    }
    g_aL[row * H1 + h] = sL;
    g_aR[row * H1 + h] = sR;
}

// ---------------------------------------------------------------------------
// Kernel 2: pair GEMM.
// CTA tile: 16 i-values x 16 j-values = 256 pairs (M), N=64 (g), K=128 (h).
// Per K-chunk (KC=16): stage h1[k][m] = relu(aL_i[k] + aR_j[k]) in smem,
// stage W2 chunk, then register-blocked 8x8 GEMM per thread.
// Epilogue: +b2, relu, dot with W3, reduce across the 8 n-group lanes,
// write only strict-upper-triangle entries (rest already zeroed).
// ---------------------------------------------------------------------------
#define TI 16
#define TJ 16
#define MT 256   // TI*TJ
#define KC 16

__global__ void __launch_bounds__(256, 2)
pair_kernel(const float* __restrict__ W2,
            const float* __restrict__ b2,
            const float* __restrict__ W3,
            const float* __restrict__ b3,
            float* __restrict__ out) {
    const int jt = blockIdx.x;     // j tile
    const int it = blockIdx.y;     // i tile
    const int b  = blockIdx.z;
    if (jt < it) return;           // strict lower tiles: nothing to do

    const int i0 = it * TI;
    const int j0 = jt * TJ;
    const int tid = threadIdx.x;   // 0..255

    __shared__ float sA[TI][H1 + 1];   // aL rows (b1 folded), padded
    __shared__ float sR[TJ][H1 + 1];   // aR rows, padded
    __shared__ float sW[KC][H2];       // W2 K-chunk
    __shared__ float sH[KC][MT];       // h1 chunk: [k][pair]

    // load aL / aR tiles (16 rows x 128 each)
    for (int idx = tid; idx < TI * H1; idx += 256) {
        int r = idx >> 7, c = idx & 127;
        sA[r][c] = g_aL[((b * Nn + i0 + r) << 7) + c];
        sR[r][c] = g_aR[((b * Nn + j0 + r) << 7) + c];
    }
    __syncthreads();

    // thread micro-tile: 8 pairs x 8 g's
    const int mg = tid >> 3;          // 0..31
    const int ng = tid & 7;           // 0..7
    const int m0 = mg << 3;
    const int g0 = ng << 3;

    float acc[8][8];
#pragma unroll
    for (int a = 0; a < 8; a++)
#pragma unroll
        for (int g = 0; g < 8; g++) acc[a][g] = 0.f;

    const int il_s = tid >> 4;        // staging: this thread's i-local
    const int jl_s = tid & 15;        // staging: this thread's j-local

    for (int kc = 0; kc < H1; kc += KC) {
        // stage W2 chunk: KC*64 = 1024 floats
        for (int idx = tid; idx < KC * H2; idx += 256)
            sW[idx >> 6][idx & 63] = W2[(kc + (idx >> 6)) * H2 + (idx & 63)];
        // stage h1 chunk: thread handles pair m=tid for all KC k's
#pragma unroll
        for (int k = 0; k < KC; k++) {
            float v = sA[il_s][kc + k] + sR[jl_s][kc + k];
            sH[k][tid] = fmaxf(v, 0.f);
        }
        __syncthreads();

#pragma unroll 4
        for (int k = 0; k < KC; k++) {
            float av[8], bv[8];
            *(float4*)&av[0] = *(const float4*)&sH[k][m0];
            *(float4*)&av[4] = *(const float4*)&sH[k][m0 + 4];
            *(float4*)&bv[0] = *(const float4*)&sW[k][g0];
            *(float4*)&bv[4] = *(const float4*)&sW[k][g0 + 4];
#pragma unroll
            for (int a = 0; a < 8; a++)
#pragma unroll
                for (int g = 0; g < 8; g++)
                    acc[a][g] = fmaf(av[a], bv[g], acc[a][g]);
        }
        __syncthreads();
    }

    // epilogue: h2 = relu(acc + b2), y = h2 . W3
    float b2v[8], w3v[8];
#pragma unroll
    for (int g = 0; g < 8; g++) {
        b2v[g] = b2[g0 + g];
        w3v[g] = W3[g0 + g];
    }
    float yv[8];
#pragma unroll
    for (int a = 0; a < 8; a++) {
        float s = 0.f;
#pragma unroll
        for (int g = 0; g < 8; g++) {
            float h2 = fmaxf(acc[a][g] + b2v[g], 0.f);
            s = fmaf(h2, w3v[g], s);
        }
        yv[a] = s;
    }
    // reduce across the 8 lanes sharing the same pair group (lanes ng=0..7)
#pragma unroll
    for (int off = 4; off > 0; off >>= 1)
#pragma unroll
        for (int a = 0; a < 8; a++)
            yv[a] += __shfl_down_sync(0xFFFFFFFFu, yv[a], off);

    if (ng == 0) {
        float b3v = b3[0];
        int il = m0 >> 4;          // pairs m0..m0+7 share one i-local
        int jbase = m0 & 15;       // 0 or 8
        int gi = i0 + il;
        long base = ((long)(b * Nn + gi)) * Nn;
#pragma unroll
        for (int a = 0; a < 8; a++) {
            int gj = j0 + jbase + a;
            if (gj > gi) out[base + gj] = yv[a] + b3v;
        }
    }
}

// ---------------------------------------------------------------------------
extern "C" void kernel_launch(void* const* d_in, const int* in_sizes, int n_in,
                              void* d_out, int out_size) {
    const float* x  = (const float*)d_in[0];
    const float* W1 = (const float*)d_in[1];
    const float* b1 = (const float*)d_in[2];
    const float* W2 = (const float*)d_in[3];
    const float* b2 = (const float*)d_in[4];
    const float* W3 = (const float*)d_in[5];
    const float* b3 = (const float*)d_in[6];
    float* out = (float*)d_out;

    // 1) zero the full output (masked entries must be 0; buffer is poisoned)
    int n4 = (Bb * Nn * Nn) / 4;
    zero_fill_kernel<<<(n4 + 255) / 256, 256>>>((float4*)out, n4);

    // 2) precompute aL (with b1) and aR
    precompute_kernel<<<Bb * Nn, 128>>>(x, W1, b1);

    // 3) pair GEMM over upper-triangle tiles
    dim3 grid(Nn / TJ, Nn / TI, Bb);
    pair_kernel<<<grid, 256>>>(W2, b2, W3, b3, out);
}

// round 3
// speedup vs baseline: 3.2275x; 3.2275x over previous
#include <cuda_runtime.h>
#include <cstdint>

// B=2, N=1024, C=128, H1=128, H2=64
//   aL[b,i,h] = x[b,i]@W1[:C] + b1 ; aR[b,j,h] = x[b,j]@W1[C:]
//   y[b,i,j] = relu(relu(aL_i + aR_j) @ W2 + b2) @ W3 + b3   (j>i else 0)
// Pair GEMM via warp-level mma.sync tf32 (m16n8k8) — tensor pipe without
// tcgen05 (this toolchain's PTX stage targets compute_103, no 'a' features).

#define Bb 2
#define Nn 1024
#define Cc 128
#define H1 128
#define H2 64
#define NTILES (Bb * 64 * 64)   // 16x16 (i,j) tiles

// scratch (device globals: no allocation allowed)
__device__ float    g_aL[Bb * Nn * H1];   // k-permuted along h
__device__ float    g_aR[Bb * Nn * H1];   // k-permuted along h
__device__ uint32_t g_W2t[H2 * H1];       // [n][k] k-permuted, tf32 bits

__device__ __forceinline__ uint32_t f2tf32(float x) {
    uint32_t u;
    asm("cvt.rna.tf32.f32 %0, %1;" : "=r"(u) : "f"(x));
    return u;
}
// permute k within groups of 8 so (k, k+4) become adjacent: enables LDS.64
__device__ __forceinline__ int permk(int k) {
    return (k & ~7) | ((k & 3) << 1) | ((k >> 2) & 1);
}

__device__ __forceinline__ void mma_tf32(float c[4], const uint32_t a[4],
                                         uint32_t b0, uint32_t b1) {
    asm volatile(
        "mma.sync.aligned.m16n8k8.row.col.f32.tf32.tf32.f32 "
        "{%0,%1,%2,%3},{%4,%5,%6,%7},{%8,%9},{%0,%1,%2,%3};"
        : "+f"(c[0]), "+f"(c[1]), "+f"(c[2]), "+f"(c[3])
        : "r"(a[0]), "r"(a[1]), "r"(a[2]), "r"(a[3]), "r"(b0), "r"(b1));
}

// ---------------------------------------------------------------------------
__global__ void zero_fill_kernel(float4* out, int n4) {
    int i = blockIdx.x * blockDim.x + threadIdx.x;
    if (i < n4) out[i] = make_float4(0.f, 0.f, 0.f, 0.f);
}

// ---------------------------------------------------------------------------
__global__ void precompute_kernel(const float* __restrict__ x,
                                  const float* __restrict__ W1,
                                  const float* __restrict__ b1) {
    int row = blockIdx.x;          // 0 .. B*N-1
    int h = threadIdx.x;           // 0 .. 127 (k dim of pair GEMM)
    __shared__ float sx[Cc];
    sx[h] = x[row * Cc + h];
    __syncthreads();
    float sL = b1[h], sR = 0.f;
#pragma unroll 8
    for (int c = 0; c < Cc; c++) {
        float xv = sx[c];
        sL = fmaf(xv, __ldg(&W1[c * H1 + h]), sL);
        sR = fmaf(xv, __ldg(&W1[(Cc + c) * H1 + h]), sR);
    }
    int hp = permk(h);
    g_aL[row * H1 + hp] = sL;
    g_aR[row * H1 + hp] = sR;
}

// ---------------------------------------------------------------------------
__global__ void w2_convert_kernel(const float* __restrict__ W2) {
    int idx = blockIdx.x * blockDim.x + threadIdx.x;   // 0..8191
    if (idx >= H2 * H1) return;
    int k = idx >> 6;      // 0..127
    int n = idx & 63;      // 0..63
    g_W2t[n * H1 + permk(k)] = f2tf32(W2[k * H2 + n]);
}

// ---------------------------------------------------------------------------
// Persistent pair kernel. 256 threads = 8 warps. Tile 16i x 16j = 256 pairs.
// Warp w: m-tiles {il=2w, il=2w+1}, rows of each m-tile = jl (0..15).
// ---------------------------------------------------------------------------
#define W2_STRIDE 132    // uint32 per n-row (padded)
#define AR_STRIDE 132    // floats per row (padded)

struct SmemLayout {
    uint32_t w2[H2 * W2_STRIDE];   // 33792 B
    float aL[16 * H1];             //  8192 B (no pad: warp-uniform row reads)
    float aR[16 * AR_STRIDE];      //  8448 B
    float b2s[H2];
    float w3s[H2];
};
#define SMEM_BYTES sizeof(SmemLayout)

__global__ void __launch_bounds__(256, 2)
pair_kernel(const float* __restrict__ b2,
            const float* __restrict__ W3,
            const float* __restrict__ b3,
            float* __restrict__ out) {
    extern __shared__ uint8_t smem_raw[];
    SmemLayout* sm = (SmemLayout*)smem_raw;

    const int tid = threadIdx.x;
    const int wid = tid >> 5;
    const int lane = tid & 31;
    const int p = lane >> 2;       // 0..7
    const int q = lane & 3;        // 0..3

    // stage W2 (padded rows) + biases, once
    for (int i = tid; i < H2 * 32; i += 256) {       // float4 units, 32/row
        int r = i >> 5, c = i & 31;
        ((float4*)sm->w2)[r * (W2_STRIDE / 4) + c] = ((const float4*)g_W2t)[i];
    }
    if (tid < H2) {
        sm->b2s[tid] = b2[tid];
        sm->w3s[tid] = W3[tid];
    }
    const float b3v = __ldg(&b3[0]);
    __syncthreads();

    const int il0 = 2 * wid;

    for (int t = blockIdx.x; t < NTILES; t += gridDim.x) {
        const int b  = t >> 12;
        const int it = (t >> 6) & 63;
        const int jt = t & 63;
        if (jt < it) continue;                 // strictly-lower tile: skip

        // ---- stage aL (16 rows, linear) + aR (16 rows, padded) ----
        {
            const float4* sL = (const float4*)(g_aL + ((size_t)((b << 10) + it * 16) << 7));
            const float4* sR = (const float4*)(g_aR + ((size_t)((b << 10) + jt * 16) << 7));
#pragma unroll
            for (int u = 0; u < 2; u++) {
                int i4 = tid + 256 * u;        // 0..511
                ((float4*)sm->aL)[i4] = sL[i4];
                int r = i4 >> 5, c = i4 & 31;
                ((float4*)sm->aR)[r * (AR_STRIDE / 4) + c] = sR[i4];
            }
        }
        __syncthreads();

        float acc[2][8][4];
#pragma unroll
        for (int mt = 0; mt < 2; mt++)
#pragma unroll
            for (int nt = 0; nt < 8; nt++)
#pragma unroll
                for (int e = 0; e < 4; e++) acc[mt][nt][e] = 0.f;

        const float2* aLf2 = (const float2*)sm->aL;
        const float2* aRf2 = (const float2*)sm->aR;
        const uint2*  w2f2 = (const uint2*)sm->w2;

#pragma unroll 4
        for (int ks = 0; ks < 16; ks++) {
            const int kf = 4 * ks + q;   // float2 index: .x = k(8ks+q), .y = k+4
            float2 L0 = aLf2[il0 * 64 + kf];
            float2 L1 = aLf2[(il0 + 1) * 64 + kf];
            float2 R0 = aRf2[p * (AR_STRIDE / 2) + kf];
            float2 R1 = aRf2[(p + 8) * (AR_STRIDE / 2) + kf];

            uint32_t a0[4], a1[4];
            a0[0] = f2tf32(fmaxf(L0.x + R0.x, 0.f));   // row p,   k
            a0[1] = f2tf32(fmaxf(L0.x + R1.x, 0.f));   // row p+8, k
            a0[2] = f2tf32(fmaxf(L0.y + R0.y, 0.f));   // row p,   k+4
            a0[3] = f2tf32(fmaxf(L0.y + R1.y, 0.f));   // row p+8, k+4
            a1[0] = f2tf32(fmaxf(L1.x + R0.x, 0.f));
            a1[1] = f2tf32(fmaxf(L1.x + R1.x, 0.f));
            a1[2] = f2tf32(fmaxf(L1.y + R0.y, 0.f));
            a1[3] = f2tf32(fmaxf(L1.y + R1.y, 0.f));

#pragma unroll
            for (int nt = 0; nt < 8; nt++) {
                uint2 bb = w2f2[(nt * 8 + p) * (W2_STRIDE / 2) + kf];
                mma_tf32(acc[0][nt], a0, bb.x, bb.y);
                mma_tf32(acc[1][nt], a1, bb.x, bb.y);
            }
        }

        // ---- epilogue: y = b3 + sum_g relu(D+b2)*W3 ; quad reduction ----
#pragma unroll
        for (int mt = 0; mt < 2; mt++) {
            float slo = 0.f, shi = 0.f;
#pragma unroll
            for (int nt = 0; nt < 8; nt++) {
                int g0 = nt * 8 + 2 * q;
                float b20 = sm->b2s[g0], b21 = sm->b2s[g0 + 1];
                float w30 = sm->w3s[g0], w31 = sm->w3s[g0 + 1];
                slo = fmaf(fmaxf(acc[mt][nt][0] + b20, 0.f), w30, slo);
                slo = fmaf(fmaxf(acc[mt][nt][1] + b21, 0.f), w31, slo);
                shi = fmaf(fmaxf(acc[mt][nt][2] + b20, 0.f), w30, shi);
                shi = fmaf(fmaxf(acc[mt][nt][3] + b21, 0.f), w31, shi);
            }
            slo += __shfl_xor_sync(0xFFFFFFFFu, slo, 1);
            slo += __shfl_xor_sync(0xFFFFFFFFu, slo, 2);
            shi += __shfl_xor_sync(0xFFFFFFFFu, shi, 1);
            shi += __shfl_xor_sync(0xFFFFFFFFu, shi, 2);
            if (q == 0) {
                int gi = it * 16 + il0 + mt;
                int gjlo = jt * 16 + p;
                int gjhi = gjlo + 8;
                size_t base = ((size_t)((b << 10) + gi)) << 10;
                if (gjlo > gi) out[base + gjlo] = slo + b3v;
                if (gjhi > gi) out[base + gjhi] = shi + b3v;
            }
        }
        __syncthreads();   // protect aL/aR before next tile's staging
    }
}

// ---------------------------------------------------------------------------
extern "C" void kernel_launch(void* const* d_in, const int* in_sizes, int n_in,
                              void* d_out, int out_size) {
    const float* x  = (const float*)d_in[0];
    const float* W1 = (const float*)d_in[1];
    const float* b1 = (const float*)d_in[2];
    const float* W2 = (const float*)d_in[3];
    const float* b2 = (const float*)d_in[4];
    const float* W3 = (const float*)d_in[5];
    const float* b3 = (const float*)d_in[6];
    float* out = (float*)d_out;

    static bool attr_set = false;
    if (!attr_set) {
        cudaFuncSetAttribute(pair_kernel,
                             cudaFuncAttributeMaxDynamicSharedMemorySize,
                             (int)SMEM_BYTES);
        attr_set = true;
    }

    int n4 = (Bb * Nn * Nn) / 4;
    zero_fill_kernel<<<(n4 + 255) / 256, 256>>>((float4*)out, n4);
    precompute_kernel<<<Bb * Nn, 128>>>(x, W1, b1);
    w2_convert_kernel<<<(H2 * H1 + 127) / 128, 128>>>(W2);
    pair_kernel<<<304, 256, SMEM_BYTES>>>(b2, W3, b3, out);
}

// round 5
// speedup vs baseline: 3.3342x; 1.0331x over previous
#include <cuda_runtime.h>
#include <cstdint>

// B=2, N=1024, C=128, H1=128, H2=64
//   aL[b,i,h] = x[b,i]@W1[:C] + b1 ; aR[b,j,h] = x[b,j]@W1[C:]
//   y[b,i,j] = relu(relu(aL_i + aR_j) @ W2 + b2) @ W3 + b3   (j>i else 0)
// Pair GEMM via warp-level mma.sync tf32 m16n8k8 (tensor pipe; tcgen05 PTX
// is rejected by this toolchain's compute_103 stage).
// R5 = R4 with the zero-fill bounds bug fixed (ZERO_BLKS 16384 -> 4096).
// R4 theory: 32i x 16j CTA tile, 4 m-tiles per warp -> W2/aR fragments
// amortized over 4 MMAs (R3 was LDS-bound: L1 72.7% vs tensor 47.4%).

#define Bb 2
#define Nn 1024
#define Cc 128
#define H1 128
#define H2 64

#define TI 32
#define TJ 16
#define ITILES 32            // Nn/TI
#define JTILES 64            // Nn/TJ
#define NTILES (Bb * ITILES * JTILES)   // 4096

// scratch (device globals: no allocation allowed)
__device__ float    g_aL[Bb * Nn * H1];   // k-permuted along h
__device__ float    g_aR[Bb * Nn * H1];   // k-permuted along h
__device__ uint32_t g_W2t[H2 * H1];       // [n][k] k-permuted, tf32 bits

__device__ __forceinline__ uint32_t f2tf32(float x) {
    uint32_t u;
    asm("cvt.rna.tf32.f32 %0, %1;" : "=r"(u) : "f"(x));
    return u;
}
// permute k within groups of 8 so (k, k+4) become adjacent: enables LDS.64
__device__ __forceinline__ int permk(int k) {
    return (k & ~7) | ((k & 3) << 1) | ((k >> 2) & 1);
}

__device__ __forceinline__ void mma_tf32(float c[4], const uint32_t a[4],
                                         uint32_t b0, uint32_t b1) {
    asm volatile(
        "mma.sync.aligned.m16n8k8.row.col.f32.tf32.tf32.f32 "
        "{%0,%1,%2,%3},{%4,%5,%6,%7},{%8,%9},{%0,%1,%2,%3};"
        : "+f"(c[0]), "+f"(c[1]), "+f"(c[2]), "+f"(c[3])
        : "r"(a[0]), "r"(a[1]), "r"(a[2]), "r"(a[3]), "r"(b0), "r"(b1));
}

// ---------------------------------------------------------------------------
// Combined prep: [0,2048) precompute rows; [2048,2112) W2 convert;
// [2112,...) zero-fill output. One launch instead of three.
// ---------------------------------------------------------------------------
#define PREP_PRE 2048
#define PREP_W2  (PREP_PRE + 64)
// output = Bb*Nn*Nn floats = 2,097,152 floats = 524,288 float4
// 524,288 / 128 threads = 4096 blocks
#define ZERO_BLKS 4096
#define PREP_GRID (PREP_W2 + ZERO_BLKS)

__global__ void __launch_bounds__(128)
prep_kernel(const float* __restrict__ x,
            const float* __restrict__ W1,
            const float* __restrict__ b1,
            const float* __restrict__ W2,
            float4* __restrict__ out4) {
    int blk = blockIdx.x;
    int h = threadIdx.x;
    if (blk < PREP_PRE) {
        // precompute aL (b1 folded) / aR for token row `blk`
        __shared__ float sx[Cc];
        sx[h] = x[blk * Cc + h];
        __syncthreads();
        float sL = b1[h], sR = 0.f;
#pragma unroll 8
        for (int c = 0; c < Cc; c++) {
            float xv = sx[c];
            sL = fmaf(xv, __ldg(&W1[c * H1 + h]), sL);
            sR = fmaf(xv, __ldg(&W1[(Cc + c) * H1 + h]), sR);
        }
        int hp = permk(h);
        g_aL[blk * H1 + hp] = sL;
        g_aR[blk * H1 + hp] = sR;
    } else if (blk < PREP_W2) {
        int idx = (blk - PREP_PRE) * 128 + h;   // 0..8191
        int k = idx >> 6;
        int n = idx & 63;
        g_W2t[n * H1 + permk(k)] = f2tf32(W2[k * H2 + n]);
    } else {
        int i = (blk - PREP_W2) * 128 + h;      // 0..524287
        out4[i] = make_float4(0.f, 0.f, 0.f, 0.f);
    }
}

// ---------------------------------------------------------------------------
// Persistent pair kernel. 256 threads = 8 warps. Tile 32i x 16j = 512 pairs.
// Warp w owns m-tiles il = 4w .. 4w+3 (fixed i per m-tile, rows = 16 j's).
// ---------------------------------------------------------------------------
#define W2_STRIDE 132    // uint32 per n-row (padded)
#define AR_STRIDE 132    // floats per row (padded)

struct SmemLayout {
    uint32_t w2[H2 * W2_STRIDE];   // 33792 B
    float aL[TI * H1];             // 16384 B (warp-uniform row reads)
    float aR[TJ * AR_STRIDE];      //  8448 B
    float b2s[H2];
    float w3s[H2];
};
#define SMEM_BYTES sizeof(SmemLayout)

__global__ void __launch_bounds__(256, 1)
pair_kernel(const float* __restrict__ b2,
            const float* __restrict__ W3,
            const float* __restrict__ b3,
            float* __restrict__ out) {
    extern __shared__ uint8_t smem_raw[];
    SmemLayout* sm = (SmemLayout*)smem_raw;

    const int tid = threadIdx.x;
    const int wid = tid >> 5;
    const int lane = tid & 31;
    const int p = lane >> 2;       // 0..7
    const int q = lane & 3;        // 0..3

    // stage W2 (padded rows) + biases, once
    for (int i = tid; i < H2 * 32; i += 256) {       // float4 units, 32/row
        int r = i >> 5, c = i & 31;
        ((float4*)sm->w2)[r * (W2_STRIDE / 4) + c] = ((const float4*)g_W2t)[i];
    }
    if (tid < H2) {
        sm->b2s[tid] = b2[tid];
        sm->w3s[tid] = W3[tid];
    }
    const float b3v = __ldg(&b3[0]);
    __syncthreads();

    const int il0 = 4 * wid;

    for (int t = blockIdx.x; t < NTILES; t += gridDim.x) {
        const int b  = t >> 11;                 // /(32*64)
        const int it = (t >> 6) & 31;
        const int jt = t & 63;
        const int i0 = it * TI;
        const int j0 = jt * TJ;
        if (j0 + TJ - 1 <= i0) continue;        // tile fully at/below diagonal

        // ---- stage aL (32 rows, linear) + aR (16 rows, padded) ----
        {
            const float4* sL = (const float4*)(g_aL + ((size_t)((b << 10) + i0) << 7));
            const float4* sR = (const float4*)(g_aR + ((size_t)((b << 10) + j0) << 7));
#pragma unroll
            for (int u = 0; u < 4; u++)
                ((float4*)sm->aL)[tid + 256 * u] = sL[tid + 256 * u];
#pragma unroll
            for (int u = 0; u < 2; u++) {
                int i4 = tid + 256 * u;         // 0..511
                int r = i4 >> 5, c = i4 & 31;
                ((float4*)sm->aR)[r * (AR_STRIDE / 4) + c] = sR[i4];
            }
        }
        __syncthreads();

        float acc[4][8][4];
#pragma unroll
        for (int mt = 0; mt < 4; mt++)
#pragma unroll
            for (int nt = 0; nt < 8; nt++)
#pragma unroll
                for (int e = 0; e < 4; e++) acc[mt][nt][e] = 0.f;

        const float2* aLf2 = (const float2*)sm->aL;
        const float2* aRf2 = (const float2*)sm->aR;
        const uint2*  w2f2 = (const uint2*)sm->w2;

#pragma unroll 2
        for (int ks = 0; ks < 16; ks++) {
            const int kf = 4 * ks + q;   // float2 idx: .x = k(8ks+q), .y = k+4
            float2 R0 = aRf2[p * (AR_STRIDE / 2) + kf];
            float2 R1 = aRf2[(p + 8) * (AR_STRIDE / 2) + kf];

            uint32_t a[4][4];
#pragma unroll
            for (int mt = 0; mt < 4; mt++) {
                float2 L = aLf2[(il0 + mt) * 64 + kf];
                a[mt][0] = f2tf32(fmaxf(L.x + R0.x, 0.f));   // row p,   k
                a[mt][1] = f2tf32(fmaxf(L.x + R1.x, 0.f));   // row p+8, k
                a[mt][2] = f2tf32(fmaxf(L.y + R0.y, 0.f));   // row p,   k+4
                a[mt][3] = f2tf32(fmaxf(L.y + R1.y, 0.f));   // row p+8, k+4
            }

#pragma unroll
            for (int nt = 0; nt < 8; nt++) {
                uint2 bb = w2f2[(nt * 8 + p) * (W2_STRIDE / 2) + kf];
#pragma unroll
                for (int mt = 0; mt < 4; mt++)
                    mma_tf32(acc[mt][nt], a[mt], bb.x, bb.y);
            }
        }

        // ---- epilogue: y = b3 + sum_g relu(D+b2)*W3 ; quad reduction ----
#pragma unroll
        for (int mt = 0; mt < 4; mt++) {
            float slo = 0.f, shi = 0.f;
#pragma unroll
            for (int nt = 0; nt < 8; nt++) {
                int g0 = nt * 8 + 2 * q;
                float b20 = sm->b2s[g0], b21 = sm->b2s[g0 + 1];
                float w30 = sm->w3s[g0], w31 = sm->w3s[g0 + 1];
                slo = fmaf(fmaxf(acc[mt][nt][0] + b20, 0.f), w30, slo);
                slo = fmaf(fmaxf(acc[mt][nt][1] + b21, 0.f), w31, slo);
                shi = fmaf(fmaxf(acc[mt][nt][2] + b20, 0.f), w30, shi);
                shi = fmaf(fmaxf(acc[mt][nt][3] + b21, 0.f), w31, shi);
            }
            slo += __shfl_xor_sync(0xFFFFFFFFu, slo, 1);
            slo += __shfl_xor_sync(0xFFFFFFFFu, slo, 2);
            shi += __shfl_xor_sync(0xFFFFFFFFu, shi, 1);
            shi += __shfl_xor_sync(0xFFFFFFFFu, shi, 2);
            if (q == 0) {
                int gi = i0 + il0 + mt;
                int gjlo = j0 + p;
                int gjhi = gjlo + 8;
                size_t base = ((size_t)((b << 10) + gi)) << 10;
                if (gjlo > gi) out[base + gjlo] = slo + b3v;
                if (gjhi > gi) out[base + gjhi] = shi + b3v;
            }
        }
        __syncthreads();   // protect aL/aR before next tile's staging
    }
}

// ---------------------------------------------------------------------------
extern "C" void kernel_launch(void* const* d_in, const int* in_sizes, int n_in,
                              void* d_out, int out_size) {
    const float* x  = (const float*)d_in[0];
    const float* W1 = (const float*)d_in[1];
    const float* b1 = (const float*)d_in[2];
    const float* W2 = (const float*)d_in[3];
    const float* b2 = (const float*)d_in[4];
    const float* W3 = (const float*)d_in[5];
    const float* b3 = (const float*)d_in[6];
    float* out = (float*)d_out;

    cudaFuncSetAttribute(pair_kernel,
                         cudaFuncAttributeMaxDynamicSharedMemorySize,
                         (int)SMEM_BYTES);

    prep_kernel<<<PREP_GRID, 128>>>(x, W1, b1, W2, (float4*)out);
    pair_kernel<<<152, 256, SMEM_BYTES>>>(b2, W3, b3, out);
}

// round 6
// speedup vs baseline: 4.8641x; 1.4588x over previous
#include <cuda_runtime.h>
#include <cuda_fp16.h>
#include <cstdint>

// B=2, N=1024, C=128, H1=128, H2=64
//   aL[b,i,h] = x[b,i]@W1[:C] + b1 ; aR[b,j,h] = x[b,j]@W1[C:]
//   y[b,i,j] = relu(relu(aL_i + aR_j) @ W2 + b2) @ W3 + b3   (j>i else 0)
// R6: pair GEMM via mma.sync m16n8k16 fp16 (fp32 accum). R5 was issue/latency
// bound (occ 12.4%, issue 35.7%, tensor 48.5%): fp16 halves HMMA count,
// packed half2 ALU halves h1-construction cost, and 64 acc regs/thread lets
// us run 512 threads (16 warps/SM, 4/SMSP) for latency hiding.

#define Bb 2
#define Nn 1024
#define Cc 128
#define H1 128
#define H2 64

#define TI 32
#define TJ 16
#define ITILES 32                        // Nn/TI
#define JTILES 64                        // Nn/TJ
#define NTILES (Bb * ITILES * JTILES)    // 4096

// scratch (device globals; fp16 pairs, k-permuted)
__device__ __align__(16) __half2 g_aLh[Bb * Nn * 64];
__device__ __align__(16) __half2 g_aRh[Bb * Nn * 64];
__device__ __align__(16) __half2 g_W2h[H2 * 64];

// k-pair j (k=2j,2j+1) -> storage slot: within each group of 8 pairs,
// thread q's pairs (q, q+4) land at (2q, 2q+1)  => one LDS.64 per fragment.
__device__ __forceinline__ int slotperm(int j) {
    int jj = j & 7;
    return (j & ~7) | (jj < 4 ? (jj << 1) : (((jj - 4) << 1) | 1));
}

__device__ __forceinline__ uint32_t h2_relu_add(uint32_t x, uint32_t y) {
    __half2 a = *reinterpret_cast<__half2*>(&x);
    __half2 b = *reinterpret_cast<__half2*>(&y);
    __half2 r = __hmax2(__hadd2(a, b), __float2half2_rn(0.f));
    return *reinterpret_cast<uint32_t*>(&r);
}

__device__ __forceinline__ void mma_f16(float c[4], const uint32_t a[4],
                                        uint32_t b0, uint32_t b1) {
    asm volatile(
        "mma.sync.aligned.m16n8k16.row.col.f32.f16.f16.f32 "
        "{%0,%1,%2,%3},{%4,%5,%6,%7},{%8,%9},{%0,%1,%2,%3};"
        : "+f"(c[0]), "+f"(c[1]), "+f"(c[2]), "+f"(c[3])
        : "r"(a[0]), "r"(a[1]), "r"(a[2]), "r"(a[3]), "r"(b0), "r"(b1));
}

// ---------------------------------------------------------------------------
// Combined prep: [0,2048) aL/aR rows; [2048,2080) W2 convert; rest zero-fill.
// ---------------------------------------------------------------------------
#define PREP_PRE 2048
#define PREP_W2  (PREP_PRE + 32)
#define ZERO_BLKS 4096                   // 524,288 float4 / 128 threads
#define PREP_GRID (PREP_W2 + ZERO_BLKS)

__global__ void __launch_bounds__(128)
prep_kernel(const float* __restrict__ x,
            const float* __restrict__ W1,
            const float* __restrict__ b1,
            const float* __restrict__ W2,
            float4* __restrict__ out4) {
    int blk = blockIdx.x;
    int h = threadIdx.x;
    if (blk < PREP_PRE) {
        __shared__ float sx[Cc];
        __shared__ float fL[H1], fR[H1];
        sx[h] = x[blk * Cc + h];
        __syncthreads();
        float sL = b1[h], sR = 0.f;
#pragma unroll 8
        for (int c = 0; c < Cc; c++) {
            float xv = sx[c];
            sL = fmaf(xv, __ldg(&W1[c * H1 + h]), sL);
            sR = fmaf(xv, __ldg(&W1[(Cc + c) * H1 + h]), sR);
        }
        fL[h] = sL;
        fR[h] = sR;
        __syncthreads();
        if (h < 64) {
            int s = slotperm(h);
            g_aLh[blk * 64 + s] = __floats2half2_rn(fL[2 * h], fL[2 * h + 1]);
            g_aRh[blk * 64 + s] = __floats2half2_rn(fR[2 * h], fR[2 * h + 1]);
        }
    } else if (blk < PREP_W2) {
        int idx = (blk - PREP_PRE) * 128 + h;   // 0..4095
        int n = idx >> 6;                       // 0..63
        int j = idx & 63;                       // k-pair
        g_W2h[n * 64 + slotperm(j)] =
            __floats2half2_rn(W2[(2 * j) * H2 + n], W2[(2 * j + 1) * H2 + n]);
    } else {
        int i = (blk - PREP_W2) * 128 + h;      // 0..524287
        out4[i] = make_float4(0.f, 0.f, 0.f, 0.f);
    }
}

// ---------------------------------------------------------------------------
// Persistent pair kernel. 512 threads = 16 warps. Tile 32i x 16j = 512 pairs.
// Warp w owns m-tiles il = 2w, 2w+1 (fixed i per m-tile; rows = 16 j's).
// ---------------------------------------------------------------------------
#define AR_STRIDE 34     // uint2 per aR row (68 half2, padded)
#define W2_STRIDE 34     // uint2 per W2 n-row (padded)

struct SmemLayout {
    uint2 w2[H2 * W2_STRIDE];   // 17408 B
    uint2 aL[TI * 32];          //  8192 B (warp-uniform row reads, no pad)
    uint2 aR[TJ * AR_STRIDE];   //  4352 B
    float b2s[H2];
    float w3s[H2];
};

__global__ void __launch_bounds__(512, 1)
pair_kernel(const float* __restrict__ b2,
            const float* __restrict__ W3,
            const float* __restrict__ b3,
            float* __restrict__ out) {
    __shared__ SmemLayout sm;

    const int tid = threadIdx.x;
    const int wid = tid >> 5;      // 0..15
    const int lane = tid & 31;
    const int p = lane >> 2;       // 0..7
    const int q = lane & 3;        // 0..3

    // stage W2 (padded rows) + biases, once
    {
        const uint2* gW2 = (const uint2*)g_W2h;
        for (int i = tid; i < H2 * 32; i += 512) {
            int r = i >> 5, c = i & 31;
            sm.w2[r * W2_STRIDE + c] = gW2[i];
        }
        if (tid < H2) {
            sm.b2s[tid] = b2[tid];
            sm.w3s[tid] = W3[tid];
        }
    }
    const float b3v = __ldg(&b3[0]);
    __syncthreads();

    const int il0 = 2 * wid;

    for (int t = blockIdx.x; t < NTILES; t += gridDim.x) {
        const int b  = t >> 11;                 // /(32*64)
        const int it = (t >> 6) & 31;
        const int jt = t & 63;
        const int i0 = it * TI;
        const int j0 = jt * TJ;
        if (j0 + TJ - 1 <= i0) continue;        // tile fully at/below diagonal

        // ---- stage aL (32 rows, linear) + aR (16 rows, padded) ----
        {
            const uint2* sL = (const uint2*)(g_aLh + ((size_t)((b << 10) + i0) << 6));
            const uint2* sR = (const uint2*)(g_aRh + ((size_t)((b << 10) + j0) << 6));
#pragma unroll
            for (int u = 0; u < 2; u++)
                sm.aL[tid + 512 * u] = sL[tid + 512 * u];
            if (tid < 512) {
                int r = tid >> 5, c = tid & 31;
                sm.aR[r * AR_STRIDE + c] = sR[tid];
            }
        }
        __syncthreads();

        float acc[2][8][4];
#pragma unroll
        for (int mt = 0; mt < 2; mt++)
#pragma unroll
            for (int nt = 0; nt < 8; nt++)
#pragma unroll
                for (int e = 0; e < 4; e++) acc[mt][nt][e] = 0.f;

#pragma unroll
        for (int ks = 0; ks < 8; ks++) {
            const int kf = 4 * ks + q;          // uint2 index within row
            uint2 Rp  = sm.aR[p * AR_STRIDE + kf];
            uint2 Rp8 = sm.aR[(p + 8) * AR_STRIDE + kf];

            uint32_t a[2][4];
#pragma unroll
            for (int mt = 0; mt < 2; mt++) {
                uint2 La = sm.aL[(il0 + mt) * 32 + kf];
                a[mt][0] = h2_relu_add(La.x, Rp.x);    // row p,   k 2q..2q+1
                a[mt][1] = h2_relu_add(La.x, Rp8.x);   // row p+8, k 2q..2q+1
                a[mt][2] = h2_relu_add(La.y, Rp.y);    // row p,   k 2q+8..9
                a[mt][3] = h2_relu_add(La.y, Rp8.y);   // row p+8, k 2q+8..9
            }

#pragma unroll
            for (int nt = 0; nt < 8; nt++) {
                uint2 bb = sm.w2[(nt * 8 + p) * W2_STRIDE + kf];
                mma_f16(acc[0][nt], a[0], bb.x, bb.y);
                mma_f16(acc[1][nt], a[1], bb.x, bb.y);
            }
        }

        // ---- epilogue: y = b3 + sum_g relu(D+b2)*W3 ; quad reduction ----
#pragma unroll
        for (int mt = 0; mt < 2; mt++) {
            float slo = 0.f, shi = 0.f;
#pragma unroll
            for (int nt = 0; nt < 8; nt++) {
                int g0 = nt * 8 + 2 * q;
                float b20 = sm.b2s[g0], b21 = sm.b2s[g0 + 1];
                float w30 = sm.w3s[g0], w31 = sm.w3s[g0 + 1];
                slo = fmaf(fmaxf(acc[mt][nt][0] + b20, 0.f), w30, slo);
                slo = fmaf(fmaxf(acc[mt][nt][1] + b21, 0.f), w31, slo);
                shi = fmaf(fmaxf(acc[mt][nt][2] + b20, 0.f), w30, shi);
                shi = fmaf(fmaxf(acc[mt][nt][3] + b21, 0.f), w31, shi);
            }
            slo += __shfl_xor_sync(0xFFFFFFFFu, slo, 1);
            slo += __shfl_xor_sync(0xFFFFFFFFu, slo, 2);
            shi += __shfl_xor_sync(0xFFFFFFFFu, shi, 1);
            shi += __shfl_xor_sync(0xFFFFFFFFu, shi, 2);
            if (q == 0) {
                int gi = i0 + il0 + mt;
                int gjlo = j0 + p;
                int gjhi = gjlo + 8;
                size_t base = ((size_t)((b << 10) + gi)) << 10;
                if (gjlo > gi) out[base + gjlo] = slo + b3v;
                if (gjhi > gi) out[base + gjhi] = shi + b3v;
            }
        }
        __syncthreads();   // protect aL/aR before next tile's staging
    }
}

// ---------------------------------------------------------------------------
extern "C" void kernel_launch(void* const* d_in, const int* in_sizes, int n_in,
                              void* d_out, int out_size) {
    const float* x  = (const float*)d_in[0];
    const float* W1 = (const float*)d_in[1];
    const float* b1 = (const float*)d_in[2];
    const float* W2 = (const float*)d_in[3];
    const float* b2 = (const float*)d_in[4];
    const float* W3 = (const float*)d_in[5];
    const float* b3 = (const float*)d_in[6];
    float* out = (float*)d_out;

    prep_kernel<<<PREP_GRID, 128>>>(x, W1, b1, W2, (float4*)out);
    pair_kernel<<<152, 512>>>(b2, W3, b3, out);
}

// round 7
// speedup vs baseline: 5.3376x; 1.0974x over previous
#include <cuda_runtime.h>
#include <cuda_fp16.h>
#include <cstdint>

// B=2, N=1024, C=128, H1=128, H2=64
//   aL[b,i,h] = x[b,i]@W1[:C] + b1 ; aR[b,j,h] = x[b,j]@W1[C:]
//   y[b,i,j] = relu(relu(aL_i + aR_j) @ W2 + b2) @ W3 + b3   (j>i else 0)
// R7: fp16 mma m16n8k16, mt=4 per warp @ 256 threads — W2/aR fragments feed
// 4 MMAs (R6 was SMEM-bound: L1 61.6% > tensor 38.4%, W2 reloads dominant).
// Prep: 16 rows/CTA, x staged in smem -> W1 L2 traffic /16.

#define Bb 2
#define Nn 1024
#define Cc 128
#define H1 128
#define H2 64

#define TI 32
#define TJ 16
#define ITILES 32                        // Nn/TI
#define JTILES 64                        // Nn/TJ
#define NTILES (Bb * ITILES * JTILES)    // 4096

// scratch (device globals; fp16 pairs, k-permuted)
__device__ __align__(16) __half2 g_aLh[Bb * Nn * 64];
__device__ __align__(16) __half2 g_aRh[Bb * Nn * 64];
__device__ __align__(16) __half2 g_W2h[H2 * 64];

// k-pair j (k=2j,2j+1) -> storage slot: within each group of 8 pairs,
// thread q's pairs (q, q+4) land at (2q, 2q+1)  => one LDS.64 per fragment.
__device__ __forceinline__ int slotperm(int j) {
    int jj = j & 7;
    return (j & ~7) | (jj < 4 ? (jj << 1) : (((jj - 4) << 1) | 1));
}

__device__ __forceinline__ uint32_t h2_relu_add(uint32_t x, uint32_t y) {
    __half2 a = *reinterpret_cast<__half2*>(&x);
    __half2 b = *reinterpret_cast<__half2*>(&y);
    __half2 r = __hmax2(__hadd2(a, b), __float2half2_rn(0.f));
    return *reinterpret_cast<uint32_t*>(&r);
}

__device__ __forceinline__ void mma_f16(float c[4], const uint32_t a[4],
                                        uint32_t b0, uint32_t b1) {
    asm volatile(
        "mma.sync.aligned.m16n8k16.row.col.f32.f16.f16.f32 "
        "{%0,%1,%2,%3},{%4,%5,%6,%7},{%8,%9},{%0,%1,%2,%3};"
        : "+f"(c[0]), "+f"(c[1]), "+f"(c[2]), "+f"(c[3])
        : "r"(a[0]), "r"(a[1]), "r"(a[2]), "r"(a[3]), "r"(b0), "r"(b1));
}

// ---------------------------------------------------------------------------
// Combined prep (256 threads/CTA):
//   [0,128)        : aL/aR for 16 token rows per CTA (x staged in smem)
//   [128,144)      : W2 convert (4096 half2)
//   [144,144+2048) : zero-fill output (524288 float4)
// ---------------------------------------------------------------------------
#define ROW_BLKS 128
#define W2_BLKS 16
#define ZERO_BLKS 2048
#define PREP_GRID (ROW_BLKS + W2_BLKS + ZERO_BLKS)

__global__ void __launch_bounds__(256)
prep_kernel(const float* __restrict__ x,
            const float* __restrict__ W1,
            const float* __restrict__ b1,
            const float* __restrict__ W2,
            float4* __restrict__ out4) {
    const int blk = blockIdx.x;
    const int tid = threadIdx.x;

    if (blk < ROW_BLKS) {
        __shared__ float sx[16][Cc];      // 8KB
        __shared__ float res[16][256];    // 16KB: [row][side*128 + h]
        const int r0 = blk * 16;

        // stage 16 x-rows (512 float4)
        {
            const float4* x4 = (const float4*)x;
#pragma unroll
            for (int u = 0; u < 2; u++)
                ((float4*)sx)[tid + 256 * u] = x4[r0 * 32 + tid + 256 * u];
        }
        __syncthreads();

        const int side = tid >> 7;        // 0 = L, 1 = R
        const int h = tid & 127;
        const float* Wp = W1 + (side ? (Cc * H1 + h) : h);   // stride H1
        float acc[16];
        const float init = side ? 0.f : b1[h];
#pragma unroll
        for (int r = 0; r < 16; r++) acc[r] = init;

#pragma unroll 4
        for (int c = 0; c < Cc; c += 4) {
            float w0 = __ldg(&Wp[(c + 0) * H1]);
            float w1 = __ldg(&Wp[(c + 1) * H1]);
            float w2 = __ldg(&Wp[(c + 2) * H1]);
            float w3 = __ldg(&Wp[(c + 3) * H1]);
#pragma unroll
            for (int r = 0; r < 16; r++) {
                float4 sv = *(const float4*)&sx[r][c];
                float a = acc[r];
                a = fmaf(sv.x, w0, a);
                a = fmaf(sv.y, w1, a);
                a = fmaf(sv.z, w2, a);
                a = fmaf(sv.w, w3, a);
                acc[r] = a;
            }
        }
#pragma unroll
        for (int r = 0; r < 16; r++) res[r][side * 128 + h] = acc[r];
        __syncthreads();

        // repack to fp16 pairs with slot permutation (2048 half2)
#pragma unroll
        for (int u = 0; u < 8; u++) {
            int idx = tid + 256 * u;      // 0..2047
            int row = idx >> 7;
            int rem = idx & 127;
            int sd = rem >> 6;
            int j = rem & 63;
            __half2 v = __floats2half2_rn(res[row][sd * 128 + 2 * j],
                                          res[row][sd * 128 + 2 * j + 1]);
            (sd ? g_aRh : g_aLh)[(size_t)(r0 + row) * 64 + slotperm(j)] = v;
        }
    } else if (blk < ROW_BLKS + W2_BLKS) {
        int idx = (blk - ROW_BLKS) * 256 + tid;   // 0..4095
        int n = idx >> 6;                         // 0..63
        int j = idx & 63;                         // k-pair
        g_W2h[n * 64 + slotperm(j)] =
            __floats2half2_rn(W2[(2 * j) * H2 + n], W2[(2 * j + 1) * H2 + n]);
    } else {
        int i = (blk - ROW_BLKS - W2_BLKS) * 256 + tid;   // 0..524287
        out4[i] = make_float4(0.f, 0.f, 0.f, 0.f);
    }
}

// ---------------------------------------------------------------------------
// Persistent pair kernel. 256 threads = 8 warps. Tile 32i x 16j = 512 pairs.
// Warp w owns m-tiles il = 4w .. 4w+3 (fixed i per m-tile; rows = 16 j's).
// ---------------------------------------------------------------------------
#define AR_STRIDE 34     // uint2 per aR row (padded: conflict-free 8B loads)
#define W2_STRIDE 34     // uint2 per W2 n-row (padded)

struct SmemLayout {
    uint2 w2[H2 * W2_STRIDE];   // 17408 B
    uint2 aL[TI * 32];          //  8192 B (warp-uniform row reads, no pad)
    uint2 aR[TJ * AR_STRIDE];   //  4352 B
    float b2s[H2];
    float w3s[H2];
};

__global__ void __launch_bounds__(256, 1)
pair_kernel(const float* __restrict__ b2,
            const float* __restrict__ W3,
            const float* __restrict__ b3,
            float* __restrict__ out) {
    __shared__ SmemLayout sm;

    const int tid = threadIdx.x;
    const int wid = tid >> 5;      // 0..7
    const int lane = tid & 31;
    const int p = lane >> 2;       // 0..7
    const int q = lane & 3;        // 0..3

    // stage W2 (padded rows) + biases, once
    {
        const uint2* gW2 = (const uint2*)g_W2h;
        for (int i = tid; i < H2 * 32; i += 256) {
            int r = i >> 5, c = i & 31;
            sm.w2[r * W2_STRIDE + c] = gW2[i];
        }
        if (tid < H2) {
            sm.b2s[tid] = b2[tid];
            sm.w3s[tid] = W3[tid];
        }
    }
    const float b3v = __ldg(&b3[0]);
    __syncthreads();

    const int il0 = 4 * wid;

    for (int t = blockIdx.x; t < NTILES; t += gridDim.x) {
        const int b  = t >> 11;                 // /(32*64)
        const int it = (t >> 6) & 31;
        const int jt = t & 63;
        const int i0 = it * TI;
        const int j0 = jt * TJ;
        if (j0 + TJ - 1 <= i0) continue;        // tile fully at/below diagonal

        // ---- stage aL (32 rows, linear) + aR (16 rows, padded) ----
        {
            const uint2* sL = (const uint2*)(g_aLh + ((size_t)((b << 10) + i0) << 6));
            const uint2* sR = (const uint2*)(g_aRh + ((size_t)((b << 10) + j0) << 6));
#pragma unroll
            for (int u = 0; u < 4; u++)
                sm.aL[tid + 256 * u] = sL[tid + 256 * u];
#pragma unroll
            for (int u = 0; u < 2; u++) {
                int i4 = tid + 256 * u;         // 0..511
                int r = i4 >> 5, c = i4 & 31;
                sm.aR[r * AR_STRIDE + c] = sR[i4];
            }
        }
        __syncthreads();

        float acc[4][8][4];
#pragma unroll
        for (int mt = 0; mt < 4; mt++)
#pragma unroll
            for (int nt = 0; nt < 8; nt++)
#pragma unroll
                for (int e = 0; e < 4; e++) acc[mt][nt][e] = 0.f;

#pragma unroll 2
        for (int ks = 0; ks < 8; ks++) {
            const int kf = 4 * ks + q;          // uint2 index within row
            uint2 Rp  = sm.aR[p * AR_STRIDE + kf];
            uint2 Rp8 = sm.aR[(p + 8) * AR_STRIDE + kf];

            uint32_t a[4][4];
#pragma unroll
            for (int mt = 0; mt < 4; mt++) {
                uint2 La = sm.aL[(il0 + mt) * 32 + kf];
                a[mt][0] = h2_relu_add(La.x, Rp.x);    // row p,   k 2q..2q+1
                a[mt][1] = h2_relu_add(La.x, Rp8.x);   // row p+8, k 2q..2q+1
                a[mt][2] = h2_relu_add(La.y, Rp.y);    // row p,   k 2q+8..9
                a[mt][3] = h2_relu_add(La.y, Rp8.y);   // row p+8, k 2q+8..9
            }

#pragma unroll
            for (int nt = 0; nt < 8; nt++) {
                uint2 bb = sm.w2[(nt * 8 + p) * W2_STRIDE + kf];
#pragma unroll
                for (int mt = 0; mt < 4; mt++)
                    mma_f16(acc[mt][nt], a[mt], bb.x, bb.y);
            }
        }

        // ---- epilogue: y = b3 + sum_g relu(D+b2)*W3 ; quad reduction ----
#pragma unroll
        for (int mt = 0; mt < 4; mt++) {
            float slo = 0.f, shi = 0.f;
#pragma unroll
            for (int nt = 0; nt < 8; nt++) {
                int g0 = nt * 8 + 2 * q;
                float b20 = sm.b2s[g0], b21 = sm.b2s[g0 + 1];
                float w30 = sm.w3s[g0], w31 = sm.w3s[g0 + 1];
                slo = fmaf(fmaxf(acc[mt][nt][0] + b20, 0.f), w30, slo);
                slo = fmaf(fmaxf(acc[mt][nt][1] + b21, 0.f), w31, slo);
                shi = fmaf(fmaxf(acc[mt][nt][2] + b20, 0.f), w30, shi);
                shi = fmaf(fmaxf(acc[mt][nt][3] + b21, 0.f), w31, shi);
            }
            slo += __shfl_xor_sync(0xFFFFFFFFu, slo, 1);
            slo += __shfl_xor_sync(0xFFFFFFFFu, slo, 2);
            shi += __shfl_xor_sync(0xFFFFFFFFu, shi, 1);
            shi += __shfl_xor_sync(0xFFFFFFFFu, shi, 2);
            if (q == 0) {
                int gi = i0 + il0 + mt;
                int gjlo = j0 + p;
                int gjhi = gjlo + 8;
                size_t base = ((size_t)((b << 10) + gi)) << 10;
                if (gjlo > gi) out[base + gjlo] = slo + b3v;
                if (gjhi > gi) out[base + gjhi] = shi + b3v;
            }
        }
        __syncthreads();   // protect aL/aR before next tile's staging
    }
}

// ---------------------------------------------------------------------------
extern "C" void kernel_launch(void* const* d_in, const int* in_sizes, int n_in,
                              void* d_out, int out_size) {
    const float* x  = (const float*)d_in[0];
    const float* W1 = (const float*)d_in[1];
    const float* b1 = (const float*)d_in[2];
    const float* W2 = (const float*)d_in[3];
    const float* b2 = (const float*)d_in[4];
    const float* W3 = (const float*)d_in[5];
    const float* b3 = (const float*)d_in[6];
    float* out = (float*)d_out;

    prep_kernel<<<PREP_GRID, 256>>>(x, W1, b1, W2, (float4*)out);
    pair_kernel<<<152, 256>>>(b2, W3, b3, out);
}